// round 16
// baseline (speedup 1.0000x reference)
#include <cuda_runtime.h>
#include <cuda_bf16.h>
#include <cuda_fp16.h>
#include <math.h>
#include <stdint.h>

#define Bb 2
#define Dd 256
#define Nn 8192
#define CIc 128
#define Mm 4096
#define LOG2E 1.4426950408889634f

// proj smem strides (fp32 words)
#define WS  36
#define FS  136
// attention / wconv strides in halfwords
#define THH 136   // theta [q][c] fp16   (68 words: 68 mod 32 = 4 -> conflict-free)
#define PHH 136   // phi   [k][c] fp16
#define GH  72    // g     [c][k] bf16   (36 words: 4grp+tig distinct)
#define WWH 136   // wconv tiles [row][c] fp16

// -------- scratch (static device globals; no runtime allocation) --------
__device__ float          d_theta[Bb*CIc*Nn];  // (B, CI, N) fp32
__device__ __half         d_phT[Bb*Mm*CIc];    // pooled phi, (B, M, CI) fp16
__device__ __nv_bfloat16  d_gbf[Bb*CIc*Mm];    // pooled g,   (B, CI, M) bf16
__device__ float          d_y[Bb*CIc*Nn];      // attention output (B, CI, N)
__device__ float          d_Wy[Bb*Dd*Nn];      // W conv output (B, D, N)
__device__ double         d_acc[4*Dd];         // BN partial sums per (b, d)
__device__ float          d_stats[2*Dd];       // per-channel mean, inv_std

// ---------------- helpers ----------------
__device__ __forceinline__ float tf32r(float x) {
    uint32_t u;
    asm("cvt.rna.tf32.f32 %0, %1;" : "=r"(u) : "f"(x));
    return __uint_as_float(u);
}

__device__ __forceinline__ void mma_tf32(float* d, const uint32_t* a,
                                         uint32_t b0, uint32_t b1) {
    asm volatile(
        "mma.sync.aligned.m16n8k8.row.col.f32.tf32.tf32.f32 "
        "{%0,%1,%2,%3},{%4,%5,%6,%7},{%8,%9},{%0,%1,%2,%3};"
        : "+f"(d[0]), "+f"(d[1]), "+f"(d[2]), "+f"(d[3])
        : "r"(a[0]), "r"(a[1]), "r"(a[2]), "r"(a[3]), "r"(b0), "r"(b1));
}

__device__ __forceinline__ void mma_f16(float* d, const uint32_t* a,
                                        uint32_t b0, uint32_t b1) {
    asm volatile(
        "mma.sync.aligned.m16n8k16.row.col.f32.f16.f16.f32 "
        "{%0,%1,%2,%3},{%4,%5,%6,%7},{%8,%9},{%0,%1,%2,%3};"
        : "+f"(d[0]), "+f"(d[1]), "+f"(d[2]), "+f"(d[3])
        : "r"(a[0]), "r"(a[1]), "r"(a[2]), "r"(a[3]), "r"(b0), "r"(b1));
}

__device__ __forceinline__ void mma_bf16(float* d, const uint32_t* a,
                                         uint32_t b0, uint32_t b1) {
    asm volatile(
        "mma.sync.aligned.m16n8k16.row.col.f32.bf16.bf16.f32 "
        "{%0,%1,%2,%3},{%4,%5,%6,%7},{%8,%9},{%0,%1,%2,%3};"
        : "+f"(d[0]), "+f"(d[1]), "+f"(d[2]), "+f"(d[3])
        : "r"(a[0]), "r"(a[1]), "r"(a[2]), "r"(a[3]), "r"(b0), "r"(b1));
}

__device__ __forceinline__ void cp16(uint32_t dst, const void* src) {
    asm volatile("cp.async.cg.shared.global [%0], [%1], 16;\n"
                 :: "r"(dst), "l"(src));
}

// ============================================================================
// Kernel 1: three 1x1-conv projections on tensor cores (tf32).
// theta -> fp32 (B,CI,N); g -> bf16 (B,CI,M) pooled; phi -> fp16 (B,M,CI) pooled.
// ============================================================================
__global__ __launch_bounds__(256) void proj_tc(
    const float* __restrict__ f,
    const float* __restrict__ gw, const float* __restrict__ gb,
    const float* __restrict__ tw, const float* __restrict__ tb,
    const float* __restrict__ pw, const float* __restrict__ pb)
{
    const int zi = blockIdx.y;
    const float* W  = (zi == 0) ? tw : (zi == 1) ? gw : pw;
    const float* bs = (zi == 0) ? tb : (zi == 1) ? gb : pb;

    const int b    = blockIdx.z;
    const int n0   = blockIdx.x * 128;
    const int tid  = threadIdx.x;
    const int warp = tid >> 5;
    const int lane = tid & 31;
    const int grp  = lane >> 2;
    const int tig  = lane & 3;
    const int Cw   = (warp >> 1) * 32;
    const int Nw   = (warp & 1) * 64;

    __shared__ float w_sm[128 * WS];
    __shared__ float f_sm[32 * FS];
    const uint32_t* wu = (const uint32_t*)w_sm;
    const uint32_t* fu = (const uint32_t*)f_sm;

    float acc[2][8][4];
    #pragma unroll
    for (int mt = 0; mt < 2; mt++)
        #pragma unroll
        for (int nt = 0; nt < 8; nt++)
            #pragma unroll
            for (int r = 0; r < 4; r++) acc[mt][nt][r] = 0.f;

    const float* fb = f + (size_t)b * Dd * Nn;

    for (int d0 = 0; d0 < Dd; d0 += 32) {
        __syncthreads();
        #pragma unroll
        for (int r = 0; r < 2; r++) {
            int idx = (tid + r * 256) * 8;
            int c = idx >> 5, dl = idx & 31;
            float4 v0 = *(const float4*)&W[c * Dd + d0 + dl];
            float4 v1 = *(const float4*)&W[c * Dd + d0 + dl + 4];
            *(float4*)&w_sm[c * WS + dl] =
                make_float4(tf32r(v0.x), tf32r(v0.y), tf32r(v0.z), tf32r(v0.w));
            *(float4*)&w_sm[c * WS + dl + 4] =
                make_float4(tf32r(v1.x), tf32r(v1.y), tf32r(v1.z), tf32r(v1.w));
        }
        #pragma unroll
        for (int r = 0; r < 4; r++) {
            int idx = (tid + r * 256) * 4;
            int dd2 = idx >> 7, nn2 = idx & 127;
            float4 v = *(const float4*)&fb[(size_t)(d0 + dd2) * Nn + n0 + nn2];
            *(float4*)&f_sm[dd2 * FS + nn2] =
                make_float4(tf32r(v.x), tf32r(v.y), tf32r(v.z), tf32r(v.w));
        }
        __syncthreads();

        #pragma unroll
        for (int k8 = 0; k8 < 4; k8++) {
            const int col = k8 * 8 + tig;
            uint32_t A[2][4];
            #pragma unroll
            for (int mt = 0; mt < 2; mt++) {
                int rb = Cw + mt * 16 + grp;
                A[mt][0] = wu[(rb    ) * WS + col    ];
                A[mt][1] = wu[(rb + 8) * WS + col    ];
                A[mt][2] = wu[(rb    ) * WS + col + 4];
                A[mt][3] = wu[(rb + 8) * WS + col + 4];
            }
            #pragma unroll
            for (int nt = 0; nt < 8; nt++) {
                uint32_t b0 = fu[(col    ) * FS + Nw + nt * 8 + grp];
                uint32_t b1 = fu[(col + 4) * FS + Nw + nt * 8 + grp];
                mma_tf32(acc[0][nt], A[0], b0, b1);
                mma_tf32(acc[1][nt], A[1], b0, b1);
            }
        }
    }

    if (zi == 0) {          // theta: fp32 (B, CI, N)
        #pragma unroll
        for (int mt = 0; mt < 2; mt++) {
            int c = Cw + mt * 16 + grp;
            float bias0 = bs[c], bias1 = bs[c + 8];
            #pragma unroll
            for (int nt = 0; nt < 8; nt++) {
                int n = n0 + Nw + nt * 8 + 2 * tig;
                *(float2*)&d_theta[((size_t)b * CIc + c) * Nn + n] =
                    make_float2(acc[mt][nt][0] + bias0, acc[mt][nt][1] + bias0);
                *(float2*)&d_theta[((size_t)b * CIc + c + 8) * Nn + n] =
                    make_float2(acc[mt][nt][2] + bias1, acc[mt][nt][3] + bias1);
            }
        }
    } else if (zi == 1) {   // g: maxpool2 -> bf16 (B, CI, M)
        #pragma unroll
        for (int mt = 0; mt < 2; mt++) {
            int c = Cw + mt * 16 + grp;
            float bias0 = bs[c], bias1 = bs[c + 8];
            #pragma unroll
            for (int nt = 0; nt < 8; nt++) {
                int m = (n0 + Nw) / 2 + nt * 4 + tig;
                d_gbf[((size_t)b * CIc + c) * Mm + m] =
                    __float2bfloat16_rn(fmaxf(acc[mt][nt][0], acc[mt][nt][1]) + bias0);
                d_gbf[((size_t)b * CIc + c + 8) * Mm + m] =
                    __float2bfloat16_rn(fmaxf(acc[mt][nt][2], acc[mt][nt][3]) + bias1);
            }
        }
    } else {                // phi: maxpool2 -> fp16 (B, M, CI)
        #pragma unroll
        for (int mt = 0; mt < 2; mt++) {
            int c = Cw + mt * 16 + grp;
            float bias0 = bs[c], bias1 = bs[c + 8];
            #pragma unroll
            for (int nt = 0; nt < 8; nt++) {
                int m = (n0 + Nw) / 2 + nt * 4 + tig;
                d_phT[((size_t)b * Mm + m) * CIc + c] =
                    __float2half_rn(fmaxf(acc[mt][nt][0], acc[mt][nt][1]) + bias0);
                d_phT[((size_t)b * Mm + m) * CIc + c + 8] =
                    __float2half_rn(fmaxf(acc[mt][nt][2], acc[mt][nt][3]) + bias1);
            }
        }
    }
}

// ============================================================================
// Kernel 2: sync-free tensor-core attention.
// Warp owns 16 q x all 64 k of each chunk. GEMM1 fp16 (theta pre-scaled by
// log2e, exp = single ex2). P stays in registers (C-frag == A-frag layout).
// GEMM2 bf16. B-fragments via ldmatrix.x4. One __syncthreads per chunk.
// ============================================================================
#define SM_TH 0
#define SM_PH (128 * THH * 2)                 // 34816
#define SM_GG (SM_PH + 2 * 64 * PHH * 2)      // 69632
#define SM_ATTN (SM_GG + 2 * 128 * GH * 2)    // 106496

__global__ __launch_bounds__(256, 1) void attn_kernel()
{
    extern __shared__ char smc[];
    __half* th = (__half*)(smc + SM_TH);
    const uint32_t smb = (uint32_t)__cvta_generic_to_shared(smc);

    const int b    = blockIdx.y;
    const int q0g  = blockIdx.x * 128;
    const int tid  = threadIdx.x;
    const int warp = tid >> 5;
    const int lane = tid & 31;
    const int grp  = lane >> 2;
    const int tig  = lane & 3;
    const int QB   = warp * 16;
    // ldmatrix lane address components (B-operand mode: m0/m1 rows lo, m2/m3 +8)
    const int lrow = ((lane >> 4) << 3) + (lane & 7);
    const int lcol = ((lane >> 3) & 1) * 8;

    const float*         theta = d_theta + (size_t)b * CIc * Nn;
    const __half*        phg   = d_phT   + (size_t)b * Mm * CIc;
    const __nv_bfloat16* ggm   = d_gbf   + (size_t)b * CIc * Mm;

    // ---- issue prefetch of chunk 0 (overlaps theta prologue) ----
    #pragma unroll
    for (int r = 0; r < 4; r++) {
        int gI = tid + r * 256;
        int k = gI >> 4, off = (gI & 15) * 8;
        cp16(smb + SM_PH + (k * PHH + off) * 2, phg + (size_t)k * CIc + off);
        int c = gI >> 3, o2 = (gI & 7) * 8;
        cp16(smb + SM_GG + (c * GH + o2) * 2, ggm + (size_t)c * Mm + o2);
    }
    asm volatile("cp.async.commit_group;");

    // ---- theta prologue: [q][c] fp16, pre-scaled by log2(e) ----
    #pragma unroll
    for (int r = 0; r < 16; r++) {
        int idx = (tid + r * 256) * 4;
        int c = idx >> 7, q = idx & 127;
        float4 v = *(const float4*)&theta[(size_t)c * Nn + q0g + q];
        th[(q + 0) * THH + c] = __float2half_rn(v.x * LOG2E);
        th[(q + 1) * THH + c] = __float2half_rn(v.y * LOG2E);
        th[(q + 2) * THH + c] = __float2half_rn(v.z * LOG2E);
        th[(q + 3) * THH + c] = __float2half_rn(v.w * LOG2E);
    }
    __syncthreads();

    // ---- cache ALL theta A-fragments (8 k16 steps x 4 regs) ----
    uint32_t Ac[8][4];
    #pragma unroll
    for (int c8 = 0; c8 < 8; c8++) {
        const int co = c8 * 16 + 2 * tig;
        Ac[c8][0] = *(const uint32_t*)&th[(QB + grp    ) * THH + co    ];
        Ac[c8][1] = *(const uint32_t*)&th[(QB + grp + 8) * THH + co    ];
        Ac[c8][2] = *(const uint32_t*)&th[(QB + grp    ) * THH + co + 8];
        Ac[c8][3] = *(const uint32_t*)&th[(QB + grp + 8) * THH + co + 8];
    }

    float yacc[16][4];
    #pragma unroll
    for (int nt = 0; nt < 16; nt++)
        #pragma unroll
        for (int r = 0; r < 4; r++) yacc[nt][r] = 0.f;
    float lsum0 = 0.f, lsum1 = 0.f;

    for (int ic = 0; ic < Mm / 64; ic++) {
        const int buf = ic & 1;
        asm volatile("cp.async.wait_group 0;");
        __syncthreads();

        if (ic + 1 < Mm / 64) {
            const int k0n = (ic + 1) * 64;
            const uint32_t phd = smb + SM_PH + (buf ^ 1) * 64 * PHH * 2;
            const uint32_t ggd = smb + SM_GG + (buf ^ 1) * 128 * GH * 2;
            const __half*        phs = phg + (size_t)k0n * CIc;
            const __nv_bfloat16* ggs = ggm + k0n;
            #pragma unroll
            for (int r = 0; r < 4; r++) {
                int gI = tid + r * 256;
                int k = gI >> 4, off = (gI & 15) * 8;
                cp16(phd + (k * PHH + off) * 2, phs + (size_t)k * CIc + off);
                int c = gI >> 3, o2 = (gI & 7) * 8;
                cp16(ggd + (c * GH + o2) * 2, ggs + (size_t)c * Mm + o2);
            }
            asm volatile("cp.async.commit_group;");
        }

        const uint32_t phb = smb + SM_PH + buf * 64 * PHH * 2;
        const uint32_t ggb = smb + SM_GG + buf * 128 * GH * 2;

        // ---- GEMM1: S[16q x 64k] (fp16, base-2 logits) ----
        float s[8][4];
        #pragma unroll
        for (int nt = 0; nt < 8; nt++)
            #pragma unroll
            for (int r = 0; r < 4; r++) s[nt][r] = 0.f;

        #pragma unroll
        for (int c8 = 0; c8 < 8; c8++) {
            #pragma unroll
            for (int ntp = 0; ntp < 4; ntp++) {
                uint32_t r0, r1, r2, r3;
                asm volatile("ldmatrix.sync.aligned.m8n8.x4.shared.b16 {%0,%1,%2,%3}, [%4];"
                             : "=r"(r0), "=r"(r1), "=r"(r2), "=r"(r3)
                             : "r"(phb + ((ntp * 16 + lrow) * PHH + c8 * 16 + lcol) * 2));
                mma_f16(s[2 * ntp    ], Ac[c8], r0, r1);
                mma_f16(s[2 * ntp + 1], Ac[c8], r2, r3);
            }
        }

        // ---- exp (ex2) in registers, pack bf16 A-frags, row sums ----
        #pragma unroll
        for (int nt = 0; nt < 8; nt++) {
            #pragma unroll
            for (int r = 0; r < 4; r++) {
                float y;
                asm("ex2.approx.f32 %0, %1;" : "=f"(y) : "f"(s[nt][r]));
                s[nt][r] = y;
            }
            lsum0 += s[nt][0] + s[nt][1];
            lsum1 += s[nt][2] + s[nt][3];
        }
        uint32_t Pa[4][4];
        #pragma unroll
        for (int kk = 0; kk < 4; kk++) {
            __nv_bfloat162 b0 = __floats2bfloat162_rn(s[2 * kk    ][0], s[2 * kk    ][1]);
            __nv_bfloat162 b1 = __floats2bfloat162_rn(s[2 * kk    ][2], s[2 * kk    ][3]);
            __nv_bfloat162 b2 = __floats2bfloat162_rn(s[2 * kk + 1][0], s[2 * kk + 1][1]);
            __nv_bfloat162 b3 = __floats2bfloat162_rn(s[2 * kk + 1][2], s[2 * kk + 1][3]);
            Pa[kk][0] = *reinterpret_cast<uint32_t*>(&b0);
            Pa[kk][1] = *reinterpret_cast<uint32_t*>(&b1);
            Pa[kk][2] = *reinterpret_cast<uint32_t*>(&b2);
            Pa[kk][3] = *reinterpret_cast<uint32_t*>(&b3);
        }

        // ---- GEMM2: Y[16q x 128c] += P . g^T (bf16) ----
        #pragma unroll
        for (int kk = 0; kk < 4; kk++) {
            #pragma unroll
            for (int ntp = 0; ntp < 8; ntp++) {
                uint32_t r0, r1, r2, r3;
                asm volatile("ldmatrix.sync.aligned.m8n8.x4.shared.b16 {%0,%1,%2,%3}, [%4];"
                             : "=r"(r0), "=r"(r1), "=r"(r2), "=r"(r3)
                             : "r"(ggb + ((ntp * 16 + lrow) * GH + kk * 16 + lcol) * 2));
                mma_bf16(yacc[2 * ntp    ], Pa[kk], r0, r1);
                mma_bf16(yacc[2 * ntp + 1], Pa[kk], r2, r3);
            }
        }
    }

    // ---- normalize + store y as fp32 (B, CI, N) ----
    lsum0 += __shfl_xor_sync(0xffffffffu, lsum0, 1);
    lsum0 += __shfl_xor_sync(0xffffffffu, lsum0, 2);
    lsum1 += __shfl_xor_sync(0xffffffffu, lsum1, 1);
    lsum1 += __shfl_xor_sync(0xffffffffu, lsum1, 2);
    const float inv0 = 1.f / lsum0, inv1 = 1.f / lsum1;

    float* yb = d_y + (size_t)b * CIc * Nn;
    #pragma unroll
    for (int nt = 0; nt < 16; nt++) {
        int c0 = nt * 8 + 2 * tig;
        int q_lo = q0g + QB + grp, q_hi = q_lo + 8;
        yb[(size_t)(c0    ) * Nn + q_lo] = yacc[nt][0] * inv0;
        yb[(size_t)(c0 + 1) * Nn + q_lo] = yacc[nt][1] * inv0;
        yb[(size_t)(c0    ) * Nn + q_hi] = yacc[nt][2] * inv1;
        yb[(size_t)(c0 + 1) * Nn + q_hi] = yacc[nt][3] * inv1;
    }
}

// ============================================================================
// Kernel 3: W 1x1 conv on tensor cores (tf32). Wy = Ww(256x128) @ y + Wb.
// CTA tile: 128d x 128n, K = CI = 128. grid (N/128, D/128, B).
// ============================================================================
__global__ __launch_bounds__(256) void wconv_tc(
    const float* __restrict__ Ww, const float* __restrict__ Wb)
{
    const int b    = blockIdx.z;
    const int dblk = blockIdx.y * 128;
    const int n0   = blockIdx.x * 128;
    const int tid  = threadIdx.x;
    const int warp = tid >> 5;
    const int lane = tid & 31;
    const int grp  = lane >> 2;
    const int tig  = lane & 3;
    const int Dw   = (warp >> 1) * 32;
    const int Nw   = (warp & 1) * 64;

    __shared__ float w_sm[128 * WS];
    __shared__ float y_sm[32 * FS];
    const uint32_t* wu = (const uint32_t*)w_sm;
    const uint32_t* yu = (const uint32_t*)y_sm;

    float acc[2][8][4];
    #pragma unroll
    for (int mt = 0; mt < 2; mt++)
        #pragma unroll
        for (int nt = 0; nt < 8; nt++)
            #pragma unroll
            for (int r = 0; r < 4; r++) acc[mt][nt][r] = 0.f;

    const float* yb = d_y + (size_t)b * CIc * Nn;

    for (int c0 = 0; c0 < CIc; c0 += 32) {
        __syncthreads();
        #pragma unroll
        for (int r = 0; r < 2; r++) {
            int idx = (tid + r * 256) * 8;
            int dl = idx >> 5, cl = idx & 31;
            float4 v0 = *(const float4*)&Ww[(size_t)(dblk + dl) * CIc + c0 + cl];
            float4 v1 = *(const float4*)&Ww[(size_t)(dblk + dl) * CIc + c0 + cl + 4];
            *(float4*)&w_sm[dl * WS + cl] =
                make_float4(tf32r(v0.x), tf32r(v0.y), tf32r(v0.z), tf32r(v0.w));
            *(float4*)&w_sm[dl * WS + cl + 4] =
                make_float4(tf32r(v1.x), tf32r(v1.y), tf32r(v1.z), tf32r(v1.w));
        }
        #pragma unroll
        for (int r = 0; r < 4; r++) {
            int idx = (tid + r * 256) * 4;
            int cc = idx >> 7, nn2 = idx & 127;
            float4 v = *(const float4*)&yb[(size_t)(c0 + cc) * Nn + n0 + nn2];
            *(float4*)&y_sm[cc * FS + nn2] =
                make_float4(tf32r(v.x), tf32r(v.y), tf32r(v.z), tf32r(v.w));
        }
        __syncthreads();

        #pragma unroll
        for (int k8 = 0; k8 < 4; k8++) {
            const int col = k8 * 8 + tig;
            uint32_t A[2][4];
            #pragma unroll
            for (int mt = 0; mt < 2; mt++) {
                int rb = Dw + mt * 16 + grp;
                A[mt][0] = wu[(rb    ) * WS + col    ];
                A[mt][1] = wu[(rb + 8) * WS + col    ];
                A[mt][2] = wu[(rb    ) * WS + col + 4];
                A[mt][3] = wu[(rb + 8) * WS + col + 4];
            }
            #pragma unroll
            for (int nt = 0; nt < 8; nt++) {
                uint32_t b0 = yu[(col    ) * FS + Nw + nt * 8 + grp];
                uint32_t b1 = yu[(col + 4) * FS + Nw + nt * 8 + grp];
                mma_tf32(acc[0][nt], A[0], b0, b1);
                mma_tf32(acc[1][nt], A[1], b0, b1);
            }
        }
    }

    #pragma unroll
    for (int mt = 0; mt < 2; mt++) {
        int d = dblk + Dw + mt * 16 + grp;
        float bias0 = Wb[d], bias1 = Wb[d + 8];
        #pragma unroll
        for (int nt = 0; nt < 8; nt++) {
            int n = n0 + Nw + nt * 8 + 2 * tig;
            *(float2*)&d_Wy[((size_t)b * Dd + d) * Nn + n] =
                make_float2(acc[mt][nt][0] + bias0, acc[mt][nt][1] + bias0);
            *(float2*)&d_Wy[((size_t)b * Dd + d + 8) * Nn + n] =
                make_float2(acc[mt][nt][2] + bias1, acc[mt][nt][3] + bias1);
        }
    }
}

// ============================================================================
// Kernel 4: BN stats — per-(d, b) partial sums (no atomics, no zeroing)
// ============================================================================
__global__ __launch_bounds__(256) void stats_kernel()
{
    __shared__ double sh[256], sh2[256];
    const int d = blockIdx.x, b = blockIdx.y, tid = threadIdx.x;
    const float4* p = (const float4*)(d_Wy + ((size_t)b * Dd + d) * Nn);
    double s = 0.0, ss = 0.0;
    #pragma unroll
    for (int r = 0; r < 8; r++) {
        float4 v = p[tid + r * 256];
        s  += (double)v.x + (double)v.y + (double)v.z + (double)v.w;
        ss += (double)v.x * v.x + (double)v.y * v.y
            + (double)v.z * v.z + (double)v.w * v.w;
    }
    sh[tid] = s; sh2[tid] = ss;
    __syncthreads();
    for (int o = 128; o > 0; o >>= 1) {
        if (tid < o) { sh[tid] += sh[tid + o]; sh2[tid] += sh2[tid + o]; }
        __syncthreads();
    }
    if (tid == 0) {
        d_acc[(b * 2    ) * Dd + d] = sh[0];
        d_acc[(b * 2 + 1) * Dd + d] = sh2[0];
    }
}

__global__ void finalize_kernel()
{
    int d = threadIdx.x;
    if (d < Dd) {
        double cnt  = (double)(Bb * Nn);
        double mean = (d_acc[d] + d_acc[2 * Dd + d]) / cnt;
        double var  = (d_acc[Dd + d] + d_acc[3 * Dd + d]) / cnt - mean * mean;
        d_stats[d]      = (float)mean;
        d_stats[Dd + d] = (float)(1.0 / sqrt(var + 1e-5));
    }
}

// ============================================================================
// Kernel 5: normalize + affine + residual
// ============================================================================
__global__ __launch_bounds__(256) void final_kernel(
    const float* __restrict__ f, const float* __restrict__ gamma,
    const float* __restrict__ beta, float* __restrict__ out)
{
    size_t i4 = (size_t)blockIdx.x * 256 + threadIdx.x;
    size_t i  = i4 * 4;
    int d = (int)((i / Nn) % Dd);
    float mean = d_stats[d];
    float inv  = d_stats[Dd + d];
    float gm = gamma[d] * inv;
    float bt = beta[d] - mean * gm;
    float4 w  = *(const float4*)&d_Wy[i];
    float4 fv = *(const float4*)&f[i];
    float4 o;
    o.x = fmaf(w.x, gm, bt) + fv.x;
    o.y = fmaf(w.y, gm, bt) + fv.y;
    o.z = fmaf(w.z, gm, bt) + fv.z;
    o.w = fmaf(w.w, gm, bt) + fv.w;
    *(float4*)&out[i] = o;
}

// ============================================================================
extern "C" void kernel_launch(void* const* d_in, const int* in_sizes, int n_in,
                              void* d_out, int out_size)
{
    const float* f   = (const float*)d_in[0];
    const float* gw  = (const float*)d_in[1];
    const float* gb  = (const float*)d_in[2];
    const float* tw  = (const float*)d_in[3];
    const float* tb  = (const float*)d_in[4];
    const float* pw  = (const float*)d_in[5];
    const float* pb  = (const float*)d_in[6];
    const float* Ww  = (const float*)d_in[7];
    const float* Wb  = (const float*)d_in[8];
    const float* gma = (const float*)d_in[9];
    const float* bta = (const float*)d_in[10];
    float* out = (float*)d_out;

    static int attr_set = 0;
    if (!attr_set) {
        cudaFuncSetAttribute(attn_kernel,
                             cudaFuncAttributeMaxDynamicSharedMemorySize, SM_ATTN);
        attr_set = 1;
    }

    proj_tc<<<dim3(Nn / 128, 3, Bb), 256>>>(f, gw, gb, tw, tb, pw, pb);
    attn_kernel<<<dim3(Nn / 128, Bb), 256, SM_ATTN>>>();
    wconv_tc<<<dim3(Nn / 128, Dd / 128, Bb), 256>>>(Ww, Wb);
    stats_kernel<<<dim3(Dd, Bb), 256>>>();
    finalize_kernel<<<1, 256>>>();
    final_kernel<<<(size_t)(Bb * Dd * Nn) / (256 * 4), 256>>>(f, gma, bta, out);
}

// round 17
// speedup vs baseline: 1.2055x; 1.2055x over previous
#include <cuda_runtime.h>
#include <cuda_bf16.h>
#include <cuda_fp16.h>
#include <math.h>
#include <stdint.h>

#define Bb 2
#define Dd 256
#define Nn 8192
#define CIc 128
#define Mm 4096
#define LOG2E 1.4426950408889634f

// proj smem strides (fp32 words)
#define WS  36
#define FS  136
// attention / wconv strides in halfwords
#define THH 136   // theta [q][c] fp16
#define PHH 136   // phi   [k][c] fp16
#define GH  72    // g     [c][k] bf16
#define WWH 136   // wconv tiles [row][c] fp16

// -------- scratch (static device globals; no runtime allocation) --------
__device__ float          d_theta[Bb*CIc*Nn];  // (B, CI, N) fp32
__device__ __half         d_phT[Bb*Mm*CIc];    // pooled phi, (B, M, CI) fp16
__device__ __nv_bfloat16  d_gbf[Bb*CIc*Mm];    // pooled g,   (B, CI, M) bf16
__device__ __half         d_yh [Bb*Nn*CIc];    // attention out, (B, N, CI) fp16
__device__ float          d_Wy[Bb*Dd*Nn];      // W conv output (B, D, N)
__device__ double         d_acc[2*Dd];         // BN sum / sumsq (self-zeroing)
__device__ float          d_stats[2*Dd];       // per-channel mean, inv_std

// ---------------- helpers ----------------
__device__ __forceinline__ float tf32r(float x) {
    uint32_t u;
    asm("cvt.rna.tf32.f32 %0, %1;" : "=r"(u) : "f"(x));
    return __uint_as_float(u);
}
__device__ __forceinline__ float ex2f(float x) {
    float y;
    asm("ex2.approx.f32 %0, %1;" : "=f"(y) : "f"(x));
    return y;
}
__device__ __forceinline__ void mma_tf32(float* d, const uint32_t* a,
                                         uint32_t b0, uint32_t b1) {
    asm volatile(
        "mma.sync.aligned.m16n8k8.row.col.f32.tf32.tf32.f32 "
        "{%0,%1,%2,%3},{%4,%5,%6,%7},{%8,%9},{%0,%1,%2,%3};"
        : "+f"(d[0]), "+f"(d[1]), "+f"(d[2]), "+f"(d[3])
        : "r"(a[0]), "r"(a[1]), "r"(a[2]), "r"(a[3]), "r"(b0), "r"(b1));
}
__device__ __forceinline__ void mma_f16(float* d, const uint32_t* a,
                                        uint32_t b0, uint32_t b1) {
    asm volatile(
        "mma.sync.aligned.m16n8k16.row.col.f32.f16.f16.f32 "
        "{%0,%1,%2,%3},{%4,%5,%6,%7},{%8,%9},{%0,%1,%2,%3};"
        : "+f"(d[0]), "+f"(d[1]), "+f"(d[2]), "+f"(d[3])
        : "r"(a[0]), "r"(a[1]), "r"(a[2]), "r"(a[3]), "r"(b0), "r"(b1));
}
__device__ __forceinline__ void mma_bf16(float* d, const uint32_t* a,
                                         uint32_t b0, uint32_t b1) {
    asm volatile(
        "mma.sync.aligned.m16n8k16.row.col.f32.bf16.bf16.f32 "
        "{%0,%1,%2,%3},{%4,%5,%6,%7},{%8,%9},{%0,%1,%2,%3};"
        : "+f"(d[0]), "+f"(d[1]), "+f"(d[2]), "+f"(d[3])
        : "r"(a[0]), "r"(a[1]), "r"(a[2]), "r"(a[3]), "r"(b0), "r"(b1));
}
__device__ __forceinline__ void ldsm4(uint32_t& r0, uint32_t& r1,
                                      uint32_t& r2, uint32_t& r3, uint32_t a) {
    asm volatile("ldmatrix.sync.aligned.m8n8.x4.shared.b16 {%0,%1,%2,%3}, [%4];"
                 : "=r"(r0), "=r"(r1), "=r"(r2), "=r"(r3) : "r"(a));
}
__device__ __forceinline__ void cp16(uint32_t dst, const void* src) {
    asm volatile("cp.async.cg.shared.global [%0], [%1], 16;\n"
                 :: "r"(dst), "l"(src));
}
__device__ __forceinline__ uint32_t packbf(float a, float b) {
    __nv_bfloat162 p = __floats2bfloat162_rn(a, b);
    return *reinterpret_cast<uint32_t*>(&p);
}

// ============================================================================
// Kernel 1: three 1x1-conv projections on tensor cores (tf32).
// theta -> fp32 (B,CI,N); g -> bf16 (B,CI,M) pooled; phi -> fp16 (B,M,CI) pooled.
// ============================================================================
__global__ __launch_bounds__(256) void proj_tc(
    const float* __restrict__ f,
    const float* __restrict__ gw, const float* __restrict__ gb,
    const float* __restrict__ tw, const float* __restrict__ tb,
    const float* __restrict__ pw, const float* __restrict__ pb)
{
    const int zi = blockIdx.y;
    const float* W  = (zi == 0) ? tw : (zi == 1) ? gw : pw;
    const float* bs = (zi == 0) ? tb : (zi == 1) ? gb : pb;

    const int b    = blockIdx.z;
    const int n0   = blockIdx.x * 128;
    const int tid  = threadIdx.x;
    const int warp = tid >> 5;
    const int lane = tid & 31;
    const int grp  = lane >> 2;
    const int tig  = lane & 3;
    const int Cw   = (warp >> 1) * 32;
    const int Nw   = (warp & 1) * 64;

    __shared__ float w_sm[128 * WS];
    __shared__ float f_sm[32 * FS];
    const uint32_t* wu = (const uint32_t*)w_sm;
    const uint32_t* fu = (const uint32_t*)f_sm;

    float acc[2][8][4];
    #pragma unroll
    for (int mt = 0; mt < 2; mt++)
        #pragma unroll
        for (int nt = 0; nt < 8; nt++)
            #pragma unroll
            for (int r = 0; r < 4; r++) acc[mt][nt][r] = 0.f;

    const float* fb = f + (size_t)b * Dd * Nn;

    for (int d0 = 0; d0 < Dd; d0 += 32) {
        __syncthreads();
        #pragma unroll
        for (int r = 0; r < 2; r++) {
            int idx = (tid + r * 256) * 8;
            int c = idx >> 5, dl = idx & 31;
            float4 v0 = *(const float4*)&W[c * Dd + d0 + dl];
            float4 v1 = *(const float4*)&W[c * Dd + d0 + dl + 4];
            *(float4*)&w_sm[c * WS + dl] =
                make_float4(tf32r(v0.x), tf32r(v0.y), tf32r(v0.z), tf32r(v0.w));
            *(float4*)&w_sm[c * WS + dl + 4] =
                make_float4(tf32r(v1.x), tf32r(v1.y), tf32r(v1.z), tf32r(v1.w));
        }
        #pragma unroll
        for (int r = 0; r < 4; r++) {
            int idx = (tid + r * 256) * 4;
            int dd2 = idx >> 7, nn2 = idx & 127;
            float4 v = *(const float4*)&fb[(size_t)(d0 + dd2) * Nn + n0 + nn2];
            *(float4*)&f_sm[dd2 * FS + nn2] =
                make_float4(tf32r(v.x), tf32r(v.y), tf32r(v.z), tf32r(v.w));
        }
        __syncthreads();

        #pragma unroll
        for (int k8 = 0; k8 < 4; k8++) {
            const int col = k8 * 8 + tig;
            uint32_t A[2][4];
            #pragma unroll
            for (int mt = 0; mt < 2; mt++) {
                int rb = Cw + mt * 16 + grp;
                A[mt][0] = wu[(rb    ) * WS + col    ];
                A[mt][1] = wu[(rb + 8) * WS + col    ];
                A[mt][2] = wu[(rb    ) * WS + col + 4];
                A[mt][3] = wu[(rb + 8) * WS + col + 4];
            }
            #pragma unroll
            for (int nt = 0; nt < 8; nt++) {
                uint32_t b0 = fu[(col    ) * FS + Nw + nt * 8 + grp];
                uint32_t b1 = fu[(col + 4) * FS + Nw + nt * 8 + grp];
                mma_tf32(acc[0][nt], A[0], b0, b1);
                mma_tf32(acc[1][nt], A[1], b0, b1);
            }
        }
    }

    if (zi == 0) {          // theta: fp32 (B, CI, N)
        #pragma unroll
        for (int mt = 0; mt < 2; mt++) {
            int c = Cw + mt * 16 + grp;
            float bias0 = bs[c], bias1 = bs[c + 8];
            #pragma unroll
            for (int nt = 0; nt < 8; nt++) {
                int n = n0 + Nw + nt * 8 + 2 * tig;
                *(float2*)&d_theta[((size_t)b * CIc + c) * Nn + n] =
                    make_float2(acc[mt][nt][0] + bias0, acc[mt][nt][1] + bias0);
                *(float2*)&d_theta[((size_t)b * CIc + c + 8) * Nn + n] =
                    make_float2(acc[mt][nt][2] + bias1, acc[mt][nt][3] + bias1);
            }
        }
    } else if (zi == 1) {   // g: maxpool2 -> bf16 (B, CI, M)
        #pragma unroll
        for (int mt = 0; mt < 2; mt++) {
            int c = Cw + mt * 16 + grp;
            float bias0 = bs[c], bias1 = bs[c + 8];
            #pragma unroll
            for (int nt = 0; nt < 8; nt++) {
                int m = (n0 + Nw) / 2 + nt * 4 + tig;
                d_gbf[((size_t)b * CIc + c) * Mm + m] =
                    __float2bfloat16_rn(fmaxf(acc[mt][nt][0], acc[mt][nt][1]) + bias0);
                d_gbf[((size_t)b * CIc + c + 8) * Mm + m] =
                    __float2bfloat16_rn(fmaxf(acc[mt][nt][2], acc[mt][nt][3]) + bias1);
            }
        }
    } else {                // phi: maxpool2 -> fp16 (B, M, CI)
        #pragma unroll
        for (int mt = 0; mt < 2; mt++) {
            int c = Cw + mt * 16 + grp;
            float bias0 = bs[c], bias1 = bs[c + 8];
            #pragma unroll
            for (int nt = 0; nt < 8; nt++) {
                int m = (n0 + Nw) / 2 + nt * 4 + tig;
                d_phT[((size_t)b * Mm + m) * CIc + c] =
                    __float2half_rn(fmaxf(acc[mt][nt][0], acc[mt][nt][1]) + bias0);
                d_phT[((size_t)b * Mm + m) * CIc + c + 8] =
                    __float2half_rn(fmaxf(acc[mt][nt][2], acc[mt][nt][3]) + bias1);
            }
        }
    }
}

// ============================================================================
// Kernel 2: sync-free tensor-core attention.
// GEMM1 fp16 (theta pre-scaled by log2e, exp = fp32 ex2); P bf16 in registers.
// GEMM2 bf16. One __syncthreads per chunk; y stored fp16 (B, N, CI).
// ============================================================================
#define SM_TH 0
#define SM_PH (128 * THH * 2)                 // 34816
#define SM_GG (SM_PH + 2 * 64 * PHH * 2)      // 69632
#define SM_ATTN (SM_GG + 2 * 128 * GH * 2)    // 106496

__global__ __launch_bounds__(256, 1) void attn_kernel()
{
    extern __shared__ char smc[];
    __half* th = (__half*)(smc + SM_TH);                 // [128 q][THH]
    const uint32_t smb = (uint32_t)__cvta_generic_to_shared(smc);

    const int b    = blockIdx.y;
    const int q0g  = blockIdx.x * 128;
    const int tid  = threadIdx.x;
    const int warp = tid >> 5;
    const int lane = tid & 31;
    const int grp  = lane >> 2;
    const int tig  = lane & 3;
    const int QB   = warp * 16;
    const int lrow = ((lane >> 4) << 3) + (lane & 7);
    const int lcol = ((lane >> 3) & 1) * 8;

    const float*         theta = d_theta + (size_t)b * CIc * Nn;
    const __half*        phg   = d_phT   + (size_t)b * Mm * CIc;
    const __nv_bfloat16* ggm   = d_gbf   + (size_t)b * CIc * Mm;

    // ---- prefetch chunk 0 ----
    #pragma unroll
    for (int r = 0; r < 4; r++) {
        int gI = tid + r * 256;
        int k = gI >> 4, off = (gI & 15) * 8;
        cp16(smb + SM_PH + (k * PHH + off) * 2, phg + (size_t)k * CIc + off);
        int c = gI >> 3, o2 = (gI & 7) * 8;
        cp16(smb + SM_GG + (c * GH + o2) * 2, ggm + (size_t)c * Mm + o2);
    }
    asm volatile("cp.async.commit_group;");

    // ---- theta prologue: [q][c] fp16, pre-scaled by log2(e) ----
    #pragma unroll
    for (int r = 0; r < 16; r++) {
        int idx = (tid + r * 256) * 4;
        int c = idx >> 7, q = idx & 127;
        float4 v = *(const float4*)&theta[(size_t)c * Nn + q0g + q];
        th[(q + 0) * THH + c] = __float2half_rn(v.x * LOG2E);
        th[(q + 1) * THH + c] = __float2half_rn(v.y * LOG2E);
        th[(q + 2) * THH + c] = __float2half_rn(v.z * LOG2E);
        th[(q + 3) * THH + c] = __float2half_rn(v.w * LOG2E);
    }
    __syncthreads();

    // ---- cache all theta A-fragments: 8 k16-steps x 4 regs ----
    uint32_t Ac[8][4];
    #pragma unroll
    for (int c8 = 0; c8 < 8; c8++) {
        const int co = c8 * 16 + 2 * tig;
        Ac[c8][0] = *(const uint32_t*)&th[(QB + grp    ) * THH + co    ];
        Ac[c8][1] = *(const uint32_t*)&th[(QB + grp + 8) * THH + co    ];
        Ac[c8][2] = *(const uint32_t*)&th[(QB + grp    ) * THH + co + 8];
        Ac[c8][3] = *(const uint32_t*)&th[(QB + grp + 8) * THH + co + 8];
    }

    float yacc[16][4];
    #pragma unroll
    for (int nt = 0; nt < 16; nt++)
        #pragma unroll
        for (int r = 0; r < 4; r++) yacc[nt][r] = 0.f;
    float lsum0 = 0.f, lsum1 = 0.f;

    for (int ic = 0; ic < Mm / 64; ic++) {
        const int buf = ic & 1;
        asm volatile("cp.async.wait_group 0;");
        __syncthreads();

        if (ic + 1 < Mm / 64) {
            const int k0n = (ic + 1) * 64;
            const uint32_t phd = smb + SM_PH + (buf ^ 1) * 64 * PHH * 2;
            const uint32_t ggd = smb + SM_GG + (buf ^ 1) * 128 * GH * 2;
            const __half*        phs = phg + (size_t)k0n * CIc;
            const __nv_bfloat16* ggs = ggm + k0n;
            #pragma unroll
            for (int r = 0; r < 4; r++) {
                int gI = tid + r * 256;
                int k = gI >> 4, off = (gI & 15) * 8;
                cp16(phd + (k * PHH + off) * 2, phs + (size_t)k * CIc + off);
                int c = gI >> 3, o2 = (gI & 7) * 8;
                cp16(ggd + (c * GH + o2) * 2, ggs + (size_t)c * Mm + o2);
            }
            asm volatile("cp.async.commit_group;");
        }

        const uint32_t phb = smb + SM_PH + buf * 64 * PHH * 2;
        const uint32_t ggb = smb + SM_GG + buf * 128 * GH * 2;

        // ---- GEMM1: S[16q x 64k] (fp16, base-2 logits) ----
        float s[8][4];
        #pragma unroll
        for (int nt = 0; nt < 8; nt++)
            #pragma unroll
            for (int r = 0; r < 4; r++) s[nt][r] = 0.f;

        #pragma unroll
        for (int c8 = 0; c8 < 8; c8++) {
            #pragma unroll
            for (int ntp = 0; ntp < 4; ntp++) {
                uint32_t r0, r1, r2, r3;
                ldsm4(r0, r1, r2, r3,
                      phb + ((ntp * 16 + lrow) * PHH + c8 * 16 + lcol) * 2);
                mma_f16(s[2 * ntp    ], Ac[c8], r0, r1);
                mma_f16(s[2 * ntp + 1], Ac[c8], r2, r3);
            }
        }

        // ---- exp (fp32 ex2) -> bf16 P in registers; consistent row sums ----
        uint32_t Pa[4][4];
        #pragma unroll
        for (int nt = 0; nt < 8; nt++) {
            uint32_t u0 = packbf(ex2f(s[nt][0]), ex2f(s[nt][1]));
            uint32_t u1 = packbf(ex2f(s[nt][2]), ex2f(s[nt][3]));
            __nv_bfloat162 p0 = *(__nv_bfloat162*)&u0;
            __nv_bfloat162 p1 = *(__nv_bfloat162*)&u1;
            lsum0 += __bfloat162float(p0.x) + __bfloat162float(p0.y);
            lsum1 += __bfloat162float(p1.x) + __bfloat162float(p1.y);
            Pa[nt >> 1][(nt & 1) * 2    ] = u0;
            Pa[nt >> 1][(nt & 1) * 2 + 1] = u1;
        }

        // ---- GEMM2: Y[16q x 128c] += P . g^T (bf16) ----
        #pragma unroll
        for (int kk = 0; kk < 4; kk++) {
            #pragma unroll
            for (int ntp = 0; ntp < 8; ntp++) {
                uint32_t r0, r1, r2, r3;
                ldsm4(r0, r1, r2, r3,
                      ggb + ((ntp * 16 + lrow) * GH + kk * 16 + lcol) * 2);
                mma_bf16(yacc[2 * ntp    ], Pa[kk], r0, r1);
                mma_bf16(yacc[2 * ntp + 1], Pa[kk], r2, r3);
            }
        }
    }

    // ---- normalize + store y as fp16 (B, N, CI) ----
    lsum0 += __shfl_xor_sync(0xffffffffu, lsum0, 1);
    lsum0 += __shfl_xor_sync(0xffffffffu, lsum0, 2);
    lsum1 += __shfl_xor_sync(0xffffffffu, lsum1, 1);
    lsum1 += __shfl_xor_sync(0xffffffffu, lsum1, 2);
    const float inv0 = 1.f / lsum0, inv1 = 1.f / lsum1;

    __half* yb0 = d_yh + ((size_t)b * Nn + q0g + QB + grp) * CIc;
    __half* yb1 = yb0 + 8 * CIc;
    #pragma unroll
    for (int nt = 0; nt < 16; nt++) {
        int c = nt * 8 + 2 * tig;
        *(__half2*)&yb0[c] = __floats2half2_rn(yacc[nt][0] * inv0,
                                               yacc[nt][1] * inv0);
        *(__half2*)&yb1[c] = __floats2half2_rn(yacc[nt][2] * inv1,
                                               yacc[nt][3] * inv1);
    }
}

// ============================================================================
// Kernel 3: W conv (fp16 mma, K=128 single pass) + fused BN partial stats.
// ============================================================================
#define SM_WCONV (2 * 128 * WWH * 2 + 2 * 128 * 8)   // 71680

__global__ __launch_bounds__(256) void wconv_tc(
    const float* __restrict__ Ww, const float* __restrict__ Wb)
{
    extern __shared__ char smc[];
    __half* wsm = (__half*)smc;                        // [128 d][WWH]
    double* shs = (double*)(smc + 2 * 128 * WWH * 2);  // [128]
    double* shq = shs + 128;                           // [128]
    const uint32_t smb = (uint32_t)__cvta_generic_to_shared(smc);
    const uint32_t ysb = smb + 128 * WWH * 2;

    const int b    = blockIdx.z;
    const int dblk = blockIdx.y * 128;
    const int n0   = blockIdx.x * 128;
    const int tid  = threadIdx.x;
    const int warp = tid >> 5;
    const int lane = tid & 31;
    const int grp  = lane >> 2;
    const int tig  = lane & 3;
    const int Dw   = (warp >> 1) * 32;
    const int Nw2  = (warp & 1) * 64;
    const int lrow = ((lane >> 4) << 3) + (lane & 7);
    const int lcol = ((lane >> 3) & 1) * 8;

    // y tile (fp16 in gmem) via cp.async
    const __half* yh = d_yh + ((size_t)b * Nn + n0) * CIc;
    #pragma unroll
    for (int r = 0; r < 8; r++) {
        int gI = tid + r * 256;
        int n = gI >> 4, off = (gI & 15) * 8;
        cp16(ysb + (n * WWH + off) * 2, yh + (size_t)n * CIc + off);
    }
    asm volatile("cp.async.commit_group;");

    // Ww tile fp32 -> fp16
    #pragma unroll
    for (int r = 0; r < 16; r++) {
        int fi = tid + r * 256;
        int dl = fi >> 5, c4 = (fi & 31) * 4;
        float4 v = *(const float4*)&Ww[(size_t)(dblk + dl) * CIc + c4];
        __half2 h0 = __floats2half2_rn(v.x, v.y);
        __half2 h1 = __floats2half2_rn(v.z, v.w);
        *(__half2*)&wsm[dl * WWH + c4    ] = h0;
        *(__half2*)&wsm[dl * WWH + c4 + 2] = h1;
    }
    if (tid < 128) { shs[tid] = 0.0; shq[tid] = 0.0; }
    asm volatile("cp.async.wait_group 0;");
    __syncthreads();

    float acc[2][8][4];
    #pragma unroll
    for (int mt = 0; mt < 2; mt++)
        #pragma unroll
        for (int nt = 0; nt < 8; nt++)
            #pragma unroll
            for (int r = 0; r < 4; r++) acc[mt][nt][r] = 0.f;

    #pragma unroll
    for (int k8 = 0; k8 < 8; k8++) {
        const int co = k8 * 16 + 2 * tig;
        uint32_t A[2][4];
        #pragma unroll
        for (int mt = 0; mt < 2; mt++) {
            int rb = Dw + mt * 16 + grp;
            A[mt][0] = *(const uint32_t*)&wsm[(rb    ) * WWH + co    ];
            A[mt][1] = *(const uint32_t*)&wsm[(rb + 8) * WWH + co    ];
            A[mt][2] = *(const uint32_t*)&wsm[(rb    ) * WWH + co + 8];
            A[mt][3] = *(const uint32_t*)&wsm[(rb + 8) * WWH + co + 8];
        }
        #pragma unroll
        for (int ntp = 0; ntp < 4; ntp++) {
            uint32_t r0, r1, r2, r3;
            ldsm4(r0, r1, r2, r3,
                  ysb + ((Nw2 + ntp * 16 + lrow) * WWH + k8 * 16 + lcol) * 2);
            mma_f16(acc[0][2 * ntp    ], A[0], r0, r1);
            mma_f16(acc[1][2 * ntp    ], A[1], r0, r1);
            mma_f16(acc[0][2 * ntp + 1], A[0], r2, r3);
            mma_f16(acc[1][2 * ntp + 1], A[1], r2, r3);
        }
    }

    // epilogue: bias + store Wy + BN partials
    #pragma unroll
    for (int mt = 0; mt < 2; mt++) {
        int d0 = dblk + Dw + mt * 16 + grp;
        float bias0 = Wb[d0], bias1 = Wb[d0 + 8];
        float s0 = 0.f, q0 = 0.f, s1 = 0.f, q1 = 0.f;
        #pragma unroll
        for (int nt = 0; nt < 8; nt++) {
            int n = n0 + Nw2 + nt * 8 + 2 * tig;
            float v0 = acc[mt][nt][0] + bias0, v1 = acc[mt][nt][1] + bias0;
            float v2 = acc[mt][nt][2] + bias1, v3 = acc[mt][nt][3] + bias1;
            *(float2*)&d_Wy[((size_t)b * Dd + d0) * Nn + n] = make_float2(v0, v1);
            *(float2*)&d_Wy[((size_t)b * Dd + d0 + 8) * Nn + n] = make_float2(v2, v3);
            s0 += v0 + v1;  q0 += v0 * v0 + v1 * v1;
            s1 += v2 + v3;  q1 += v2 * v2 + v3 * v3;
        }
        s0 += __shfl_xor_sync(0xffffffffu, s0, 1);
        s0 += __shfl_xor_sync(0xffffffffu, s0, 2);
        q0 += __shfl_xor_sync(0xffffffffu, q0, 1);
        q0 += __shfl_xor_sync(0xffffffffu, q0, 2);
        s1 += __shfl_xor_sync(0xffffffffu, s1, 1);
        s1 += __shfl_xor_sync(0xffffffffu, s1, 2);
        q1 += __shfl_xor_sync(0xffffffffu, q1, 1);
        q1 += __shfl_xor_sync(0xffffffffu, q1, 2);
        if (tig == 0) {
            int ld = Dw + mt * 16 + grp;
            atomicAdd(&shs[ld],     (double)s0);
            atomicAdd(&shq[ld],     (double)q0);
            atomicAdd(&shs[ld + 8], (double)s1);
            atomicAdd(&shq[ld + 8], (double)q1);
        }
    }
    __syncthreads();
    if (tid < 128) {
        atomicAdd(&d_acc[dblk + tid],      shs[tid]);
        atomicAdd(&d_acc[Dd + dblk + tid], shq[tid]);
    }
}

// ============================================================================
// Kernel 4: finalize BN stats; self-zeroes d_acc for graph replay.
// ============================================================================
__global__ void finalize_kernel()
{
    int d = threadIdx.x;
    if (d < Dd) {
        double cnt  = (double)(Bb * Nn);
        double mean = d_acc[d] / cnt;
        double var  = d_acc[Dd + d] / cnt - mean * mean;
        d_stats[d]      = (float)mean;
        d_stats[Dd + d] = (float)(1.0 / sqrt(var + 1e-5));
        d_acc[d] = 0.0;
        d_acc[Dd + d] = 0.0;
    }
}

// ============================================================================
// Kernel 5: normalize + affine + residual
// ============================================================================
__global__ __launch_bounds__(256) void final_kernel(
    const float* __restrict__ f, const float* __restrict__ gamma,
    const float* __restrict__ beta, float* __restrict__ out)
{
    size_t i4 = (size_t)blockIdx.x * 256 + threadIdx.x;
    size_t i  = i4 * 4;
    int d = (int)((i / Nn) % Dd);
    float mean = d_stats[d];
    float inv  = d_stats[Dd + d];
    float gm = gamma[d] * inv;
    float bt = beta[d] - mean * gm;
    float4 w  = *(const float4*)&d_Wy[i];
    float4 fv = *(const float4*)&f[i];
    float4 o;
    o.x = fmaf(w.x, gm, bt) + fv.x;
    o.y = fmaf(w.y, gm, bt) + fv.y;
    o.z = fmaf(w.z, gm, bt) + fv.z;
    o.w = fmaf(w.w, gm, bt) + fv.w;
    *(float4*)&out[i] = o;
}

// ============================================================================
extern "C" void kernel_launch(void* const* d_in, const int* in_sizes, int n_in,
                              void* d_out, int out_size)
{
    const float* f   = (const float*)d_in[0];
    const float* gw  = (const float*)d_in[1];
    const float* gb  = (const float*)d_in[2];
    const float* tw  = (const float*)d_in[3];
    const float* tb  = (const float*)d_in[4];
    const float* pw  = (const float*)d_in[5];
    const float* pb  = (const float*)d_in[6];
    const float* Ww  = (const float*)d_in[7];
    const float* Wb  = (const float*)d_in[8];
    const float* gma = (const float*)d_in[9];
    const float* bta = (const float*)d_in[10];
    float* out = (float*)d_out;

    static int attr_set = 0;
    if (!attr_set) {
        cudaFuncSetAttribute(attn_kernel,
                             cudaFuncAttributeMaxDynamicSharedMemorySize, SM_ATTN);
        cudaFuncSetAttribute(wconv_tc,
                             cudaFuncAttributeMaxDynamicSharedMemorySize, SM_WCONV);
        attr_set = 1;
    }

    proj_tc<<<dim3(Nn / 128, 3, Bb), 256>>>(f, gw, gb, tw, tb, pw, pb);
    attn_kernel<<<dim3(Nn / 128, Bb), 256, SM_ATTN>>>();
    wconv_tc<<<dim3(Nn / 128, Dd / 128, Bb), 256, SM_WCONV>>>(Ww, Wb);
    finalize_kernel<<<1, 256>>>();
    final_kernel<<<(size_t)(Bb * Dd * Nn) / (256 * 4), 256>>>(f, gma, bta, out);
}